// round 14
// baseline (speedup 1.0000x reference)
#include <cuda_runtime.h>
#include <cuda_bf16.h>
#include <cstdint>

// Problem dims
#define Bn 8
#define Cn 16
#define Dn 192
#define OCn 4
#define OHn 50
#define OWn 200
#define Kbig (Cn*Dn)   // 3072

typedef __nv_bfloat16 bf16;

#define R_ELEMS ((size_t)Cn*Cn*Dn*Dn)
#define T_ELEMS ((size_t)Bn*Cn*Dn*Kbig)
#define Y_ELEMS ((size_t)Bn*Cn*Dn*Dn)
#define U_ELEMS ((size_t)Bn*OCn*OHn*Kbig)

// Scratch — SAME total bytes as the verified R13 fp32 set (383 MB):
// each fp32 tensor replaced by an equal-size bf16 hi/lo pair.
__device__ __align__(256) bf16 g_Rth[R_ELEMS], g_Rtl[R_ELEMS];  // was g_Rt fp32
__device__ __align__(256) bf16 g_th [T_ELEMS], g_tl [T_ELEMS];  // was g_t  fp32
__device__ __align__(256) bf16 g_yh [Y_ELEMS], g_yl [Y_ELEMS];  // was g_y  fp32
__device__ __align__(256) bf16 g_uh [U_ELEMS], g_ul [U_ELEMS];  // was g_u  fp32
__device__ float g_p[(size_t)4*Bn*OCn*OHn*OWn];                 // B2 split-K partials

// ---------------------------------------------------------------------------
__device__ __forceinline__ void f2bf(float v, bf16& h, bf16& l) {
    h = __float2bfloat16_rn(v);
    l = __float2bfloat16_rn(v - __bfloat162float(h));
}
__device__ __forceinline__ void mma_bf16(float* c, const unsigned* a, const unsigned* b) {
    asm volatile(
        "mma.sync.aligned.m16n8k16.row.col.f32.bf16.bf16.f32 "
        "{%0,%1,%2,%3}, {%4,%5,%6,%7}, {%8,%9}, {%0,%1,%2,%3};\n"
        : "+f"(c[0]), "+f"(c[1]), "+f"(c[2]), "+f"(c[3])
        : "r"(a[0]), "r"(a[1]), "r"(a[2]), "r"(a[3]), "r"(b[0]), "r"(b[1]));
}
__device__ __forceinline__ void ldsm4(unsigned* r, unsigned addr) {
    asm volatile("ldmatrix.sync.aligned.m8n8.x4.shared.b16 {%0,%1,%2,%3}, [%4];\n"
                 : "=r"(r[0]), "=r"(r[1]), "=r"(r[2]), "=r"(r[3]) : "r"(addr));
}
__device__ __forceinline__ void ldsm4t(unsigned* r, unsigned addr) {
    asm volatile("ldmatrix.sync.aligned.m8n8.x4.trans.shared.b16 {%0,%1,%2,%3}, [%4];\n"
                 : "=r"(r[0]), "=r"(r[1]), "=r"(r[2]), "=r"(r[3]) : "r"(addr));
}

// ---------------------------------------------------------------------------
// Transpose-convert: Rt[i][j][q][n] = R[i][j][n][q], fp32 -> hi/lo bf16
// (same values the old in-loop f2bf produced)
// ---------------------------------------------------------------------------
__global__ void k_cvtT(const float* __restrict__ R) {
    __shared__ float tile[32][33];
    const int mat = blockIdx.z;
    const float* __restrict__ src = R + (size_t)mat * Dn * Dn;
    bf16* __restrict__ dh = g_Rth + (size_t)mat * Dn * Dn;
    bf16* __restrict__ dl = g_Rtl + (size_t)mat * Dn * Dn;
    const int x0 = blockIdx.x * 32, y0 = blockIdx.y * 32;
    const int tx = threadIdx.x, ty = threadIdx.y;     // 32 x 8
    #pragma unroll
    for (int r = 0; r < 32; r += 8)
        tile[ty + r][tx] = src[(size_t)(y0 + ty + r) * Dn + x0 + tx];
    __syncthreads();
    #pragma unroll
    for (int r = 0; r < 32; r += 8) {
        bf16 h, l;
        f2bf(tile[tx][ty + r], h, l);
        size_t o = (size_t)(x0 + ty + r) * Dn + y0 + tx;
        dh[o] = h; dl[o] = l;
    }
}

// ===========================================================================
// A-stage shape (VERIFIED R13): 192x96 CTA, 256 thr, 8 warps 4m x 2n (48x48),
// BK=16, double buffer, one sync/iter. Two input flavors:
//   bgemmA_f32 : fp32 operands, in-loop f2bf (A1)
//   bgemmA_pre : pre-split hi/lo operands, pure-copy loads (A2)
// Both write hi/lo bf16 outputs from the epilogue.
// ===========================================================================
#define A_AP 40
#define A_BP 104

// -------- shared mainloop macro-parts are duplicated for clarity ----------
__device__ __forceinline__ void bgemmA_f32(
    const float* __restrict__ A, int lda,
    const float* __restrict__ Bp, int ldb,
    bf16* __restrict__ Ch, bf16* __restrict__ Cl, int ldc,
    int M, int N, int K)
{
    __shared__ __align__(16) bf16 sA [2][192][A_AP];
    __shared__ __align__(16) bf16 sBh[2][16][A_BP];
    __shared__ __align__(16) bf16 sBl[2][16][A_BP];

    const int tid  = threadIdx.x;
    const int lane = tid & 31;
    const int warp = tid >> 5;
    const int wm = warp & 3;
    const int wn = warp >> 2;
    const int col0 = blockIdx.x * 96;

    const int ar = tid >> 2;
    const int ac = (tid & 3) * 4;
    const int bact = tid < 192;
    const int br = tid / 12;
    const int bc = (tid % 12) * 8;

    float acc[3][6][4];
    #pragma unroll
    for (int t = 0; t < 3; ++t)
        #pragma unroll
        for (int n = 0; n < 6; ++n)
            #pragma unroll
            for (int e = 0; e < 4; ++e) acc[t][n][e] = 0.f;

    unsigned aAd[3], bAdH[3], bAdL[3];
    #pragma unroll
    for (int t = 0; t < 3; ++t) {
        int rr = wm * 48 + t * 16 + (lane & 15);
        int cc = (lane >> 4) * 8;
        aAd[t] = (unsigned)__cvta_generic_to_shared(&sA[0][rr][cc]);
    }
    #pragma unroll
    for (int f = 0; f < 3; ++f) {
        int rr = lane & 15;
        int cc = wn * 48 + f * 16 + (lane >> 4) * 8;
        bAdH[f] = (unsigned)__cvta_generic_to_shared(&sBh[0][rr][cc]);
        bAdL[f] = (unsigned)__cvta_generic_to_shared(&sBl[0][rr][cc]);
    }
    const unsigned aStg = 192u * A_AP * 2u;
    const unsigned bStg = 16u * A_BP * 2u;

    float4 av[3], bv[2];

    auto gload = [&](int kt) {
        #pragma unroll
        for (int p = 0; p < 3; ++p) {
            int gr = min(ar + p * 64, M - 1);
            av[p] = *reinterpret_cast<const float4*>(&A[(size_t)gr * lda + kt + ac]);
        }
        if (bact) {
            int gc = min(col0 + bc, N - 8);
            size_t bo = (size_t)(kt + br) * ldb + gc;
            bv[0] = *reinterpret_cast<const float4*>(&Bp[bo]);
            bv[1] = *reinterpret_cast<const float4*>(&Bp[bo + 4]);
        }
    };

    auto sstore = [&](int s) {
        #pragma unroll
        for (int p = 0; p < 3; ++p) {
            int r = ar + p * 64;
            bf16 h0,l0,h1,l1,h2,l2,h3,l3;
            f2bf(av[p].x, h0, l0); f2bf(av[p].y, h1, l1);
            f2bf(av[p].z, h2, l2); f2bf(av[p].w, h3, l3);
            __nv_bfloat162 q;
            q.x = h0; q.y = h1; *reinterpret_cast<__nv_bfloat162*>(&sA[s][r][ac])          = q;
            q.x = h2; q.y = h3; *reinterpret_cast<__nv_bfloat162*>(&sA[s][r][ac + 2])      = q;
            q.x = l0; q.y = l1; *reinterpret_cast<__nv_bfloat162*>(&sA[s][r][16 + ac])     = q;
            q.x = l2; q.y = l3; *reinterpret_cast<__nv_bfloat162*>(&sA[s][r][16 + ac + 2]) = q;
        }
        if (bact) {
            #pragma unroll
            for (int p = 0; p < 2; ++p) {
                bf16 h0,l0,h1,l1,h2,l2,h3,l3;
                f2bf(bv[p].x, h0, l0); f2bf(bv[p].y, h1, l1);
                f2bf(bv[p].z, h2, l2); f2bf(bv[p].w, h3, l3);
                __nv_bfloat162 q;
                int c = bc + p * 4;
                q.x = h0; q.y = h1; *reinterpret_cast<__nv_bfloat162*>(&sBh[s][br][c])     = q;
                q.x = h2; q.y = h3; *reinterpret_cast<__nv_bfloat162*>(&sBh[s][br][c + 2]) = q;
                q.x = l0; q.y = l1; *reinterpret_cast<__nv_bfloat162*>(&sBl[s][br][c])     = q;
                q.x = l2; q.y = l3; *reinterpret_cast<__nv_bfloat162*>(&sBl[s][br][c + 2]) = q;
            }
        }
    };

    const int niter = K / 16;
    gload(0);
    sstore(0);

    for (int it = 0; it < niter; ++it) {
        __syncthreads();
        if (it + 1 < niter) gload((it + 1) * 16);

        const int s = it & 1;
        const unsigned aOff = s * aStg, bOff = s * bStg;
        unsigned ah[3][4], al[3][4], bh[3][4], bl[3][4];
        #pragma unroll
        for (int t = 0; t < 3; ++t) {
            ldsm4(ah[t], aAd[t] + aOff);
            ldsm4(al[t], aAd[t] + aOff + 32);
        }
        #pragma unroll
        for (int f = 0; f < 3; ++f) {
            ldsm4t(bh[f], bAdH[f] + bOff);
            ldsm4t(bl[f], bAdL[f] + bOff);
        }
        #pragma unroll
        for (int t = 0; t < 3; ++t) {
            #pragma unroll
            for (int nt = 0; nt < 6; ++nt) {
                const unsigned* Bh = &bh[nt >> 1][(nt & 1) * 2];
                const unsigned* Bl = &bl[nt >> 1][(nt & 1) * 2];
                mma_bf16(acc[t][nt], ah[t], Bh);
                mma_bf16(acc[t][nt], ah[t], Bl);
                mma_bf16(acc[t][nt], al[t], Bh);
            }
        }
        if (it + 1 < niter) sstore((it + 1) & 1);
    }

    // epilogue: write hi/lo bf16 (same values the old in-loop split produced)
    #pragma unroll
    for (int t = 0; t < 3; ++t) {
        int mB = wm * 48 + t * 16 + (lane >> 2);
        #pragma unroll
        for (int nt = 0; nt < 6; ++nt) {
            int nB = col0 + wn * 48 + nt * 8 + (lane & 3) * 2;
            float* c = acc[t][nt];
            #pragma unroll
            for (int e = 0; e < 4; ++e) {
                int gm = mB + (e >> 1) * 8;
                int gn = nB + (e & 1);
                if (gm < M && gn < N) {
                    size_t o = (size_t)gm * ldc + gn;
                    bf16 h, l; f2bf(c[e], h, l);
                    Ch[o] = h; Cl[o] = l;
                }
            }
        }
    }
}

__device__ __forceinline__ void bgemmA_pre(
    const bf16* __restrict__ Ah, const bf16* __restrict__ Al, int lda,
    const bf16* __restrict__ Bh, const bf16* __restrict__ Bl, int ldb,
    bf16* __restrict__ Ch, bf16* __restrict__ Cl, int ldc,
    int M, int N, int K)
{
    __shared__ __align__(16) bf16 sA [2][192][A_AP];
    __shared__ __align__(16) bf16 sBh[2][16][A_BP];
    __shared__ __align__(16) bf16 sBl[2][16][A_BP];

    const int tid  = threadIdx.x;
    const int lane = tid & 31;
    const int warp = tid >> 5;
    const int wm = warp & 3;
    const int wn = warp >> 2;
    const int col0 = blockIdx.x * 96;

    const int ar = tid >> 2;
    const int ac = (tid & 3) * 4;
    const int bact = tid < 192;
    const int br = tid / 12;
    const int bc = (tid % 12) * 8;

    float acc[3][6][4];
    #pragma unroll
    for (int t = 0; t < 3; ++t)
        #pragma unroll
        for (int n = 0; n < 6; ++n)
            #pragma unroll
            for (int e = 0; e < 4; ++e) acc[t][n][e] = 0.f;

    unsigned aAd[3], bAdH[3], bAdL[3];
    #pragma unroll
    for (int t = 0; t < 3; ++t) {
        int rr = wm * 48 + t * 16 + (lane & 15);
        int cc = (lane >> 4) * 8;
        aAd[t] = (unsigned)__cvta_generic_to_shared(&sA[0][rr][cc]);
    }
    #pragma unroll
    for (int f = 0; f < 3; ++f) {
        int rr = lane & 15;
        int cc = wn * 48 + f * 16 + (lane >> 4) * 8;
        bAdH[f] = (unsigned)__cvta_generic_to_shared(&sBh[0][rr][cc]);
        bAdL[f] = (unsigned)__cvta_generic_to_shared(&sBl[0][rr][cc]);
    }
    const unsigned aStg = 192u * A_AP * 2u;
    const unsigned bStg = 16u * A_BP * 2u;

    uint2 avh[3], avl[3];
    uint4 bvh, bvl;

    auto gload = [&](int kt) {
        #pragma unroll
        for (int p = 0; p < 3; ++p) {
            int gr = min(ar + p * 64, M - 1);
            size_t go = (size_t)gr * lda + kt + ac;
            avh[p] = *reinterpret_cast<const uint2*>(Ah + go);
            avl[p] = *reinterpret_cast<const uint2*>(Al + go);
        }
        if (bact) {
            int gc = min(col0 + bc, N - 8);
            size_t bo = (size_t)(kt + br) * ldb + gc;
            bvh = *reinterpret_cast<const uint4*>(Bh + bo);
            bvl = *reinterpret_cast<const uint4*>(Bl + bo);
        }
    };

    auto sstore = [&](int s) {
        #pragma unroll
        for (int p = 0; p < 3; ++p) {
            int r = ar + p * 64;
            *reinterpret_cast<uint2*>(&sA[s][r][ac])      = avh[p];
            *reinterpret_cast<uint2*>(&sA[s][r][16 + ac]) = avl[p];
        }
        if (bact) {
            *reinterpret_cast<uint4*>(&sBh[s][br][bc]) = bvh;
            *reinterpret_cast<uint4*>(&sBl[s][br][bc]) = bvl;
        }
    };

    const int niter = K / 16;
    gload(0);
    sstore(0);

    for (int it = 0; it < niter; ++it) {
        __syncthreads();
        if (it + 1 < niter) gload((it + 1) * 16);

        const int s = it & 1;
        const unsigned aOff = s * aStg, bOff = s * bStg;
        unsigned ah[3][4], al[3][4], bh[3][4], bl[3][4];
        #pragma unroll
        for (int t = 0; t < 3; ++t) {
            ldsm4(ah[t], aAd[t] + aOff);
            ldsm4(al[t], aAd[t] + aOff + 32);
        }
        #pragma unroll
        for (int f = 0; f < 3; ++f) {
            ldsm4t(bh[f], bAdH[f] + bOff);
            ldsm4t(bl[f], bAdL[f] + bOff);
        }
        #pragma unroll
        for (int t = 0; t < 3; ++t) {
            #pragma unroll
            for (int nt = 0; nt < 6; ++nt) {
                const unsigned* Bh2 = &bh[nt >> 1][(nt & 1) * 2];
                const unsigned* Bl2 = &bl[nt >> 1][(nt & 1) * 2];
                mma_bf16(acc[t][nt], ah[t], Bh2);
                mma_bf16(acc[t][nt], ah[t], Bl2);
                mma_bf16(acc[t][nt], al[t], Bh2);
            }
        }
        if (it + 1 < niter) sstore((it + 1) & 1);
    }

    #pragma unroll
    for (int t = 0; t < 3; ++t) {
        int mB = wm * 48 + t * 16 + (lane >> 2);
        #pragma unroll
        for (int nt = 0; nt < 6; ++nt) {
            int nB = col0 + wn * 48 + nt * 8 + (lane & 3) * 2;
            float* c = acc[t][nt];
            #pragma unroll
            for (int e = 0; e < 4; ++e) {
                int gm = mB + (e >> 1) * 8;
                int gn = nB + (e & 1);
                if (gm < M && gn < N) {
                    size_t o = (size_t)gm * ldc + gn;
                    bf16 h, l; f2bf(c[e], h, l);
                    Ch[o] = h; Cl[o] = l;
                }
            }
        }
    }
}

// ===========================================================================
// B-stage shape (VERIFIED R11): 64x64 CTA, 128 threads, BK=16, dbl buffer,
// row0 fixed 0. Two flavors:
//   bgemmB_fb : A fp32 (in-loop f2bf), B pre-split  -> hi/lo out   (B1)
//   bgemmB_bf : A pre-split, B fp32 (in-loop f2bf)  -> fp32 out    (B2)
// ===========================================================================
#define B_AP 24
#define B_BP 72

__device__ __forceinline__ void bgemmB_fb(
    const float* __restrict__ A, int lda,
    const bf16* __restrict__ Bh, const bf16* __restrict__ Bl, int ldb,
    bf16* __restrict__ Ch, bf16* __restrict__ Cl, int ldc,
    int M, int N, int K)
{
    __shared__ __align__(16) bf16 sAh[2][64][B_AP];
    __shared__ __align__(16) bf16 sAl[2][64][B_AP];
    __shared__ __align__(16) bf16 sBh[2][16][B_BP];
    __shared__ __align__(16) bf16 sBl[2][16][B_BP];

    const int tid  = threadIdx.x;
    const int lane = tid & 31;
    const int warp = tid >> 5;
    const int wm = warp & 1;
    const int wn = warp >> 1;
    const int col0 = blockIdx.x * 64;

    const int ar = tid >> 1;
    const int ac = (tid & 1) * 8;
    const int br = tid >> 3;
    const int bc = (tid & 7) * 8;

    float acc[2][4][4];
    #pragma unroll
    for (int t = 0; t < 2; ++t)
        #pragma unroll
        for (int n = 0; n < 4; ++n)
            #pragma unroll
            for (int e = 0; e < 4; ++e) acc[t][n][e] = 0.f;

    unsigned aAdH[2], aAdL[2], bAdH[2], bAdL[2];
    #pragma unroll
    for (int t = 0; t < 2; ++t) {
        int rr = wm * 32 + t * 16 + (lane & 15);
        int cc = (lane >> 4) * 8;
        aAdH[t] = (unsigned)__cvta_generic_to_shared(&sAh[0][rr][cc]);
        aAdL[t] = (unsigned)__cvta_generic_to_shared(&sAl[0][rr][cc]);
    }
    #pragma unroll
    for (int p = 0; p < 2; ++p) {
        int rr = (lane & 15);
        int cc = wn * 32 + p * 16 + (lane >> 4) * 8;
        bAdH[p] = (unsigned)__cvta_generic_to_shared(&sBh[0][rr][cc]);
        bAdL[p] = (unsigned)__cvta_generic_to_shared(&sBl[0][rr][cc]);
    }
    const unsigned aStg = 64u * B_AP * 2u;
    const unsigned bStg = 16u * B_BP * 2u;

    float4 av[2];
    uint4 bvh, bvl;

    auto gload = [&](int kt) {
        int gr = min(ar, M - 1);
        #pragma unroll
        for (int p = 0; p < 2; ++p)
            av[p] = *reinterpret_cast<const float4*>(&A[(size_t)gr * lda + kt + ac + p * 4]);
        int gc = min(col0 + bc, N - 8);
        size_t bo = (size_t)(kt + br) * ldb + gc;
        bvh = *reinterpret_cast<const uint4*>(Bh + bo);
        bvl = *reinterpret_cast<const uint4*>(Bl + bo);
    };

    auto sstore = [&](int s) {
        #pragma unroll
        for (int p = 0; p < 2; ++p) {
            bf16 h0,l0,h1,l1,h2,l2,h3,l3;
            f2bf(av[p].x, h0, l0); f2bf(av[p].y, h1, l1);
            f2bf(av[p].z, h2, l2); f2bf(av[p].w, h3, l3);
            __nv_bfloat162 q;
            int c = ac + p * 4;
            q.x = h0; q.y = h1; *reinterpret_cast<__nv_bfloat162*>(&sAh[s][ar][c])     = q;
            q.x = h2; q.y = h3; *reinterpret_cast<__nv_bfloat162*>(&sAh[s][ar][c + 2]) = q;
            q.x = l0; q.y = l1; *reinterpret_cast<__nv_bfloat162*>(&sAl[s][ar][c])     = q;
            q.x = l2; q.y = l3; *reinterpret_cast<__nv_bfloat162*>(&sAl[s][ar][c + 2]) = q;
        }
        *reinterpret_cast<uint4*>(&sBh[s][br][bc]) = bvh;
        *reinterpret_cast<uint4*>(&sBl[s][br][bc]) = bvl;
    };

    const int niter = K / 16;
    gload(0);
    sstore(0);

    for (int it = 0; it < niter; ++it) {
        __syncthreads();
        if (it + 1 < niter) gload((it + 1) * 16);

        const int s = it & 1;
        const unsigned aOff = s * aStg, bOff = s * bStg;
        unsigned ah[2][4], al[2][4], bh[2][4], bl[2][4];
        #pragma unroll
        for (int t = 0; t < 2; ++t) {
            ldsm4(ah[t], aAdH[t] + aOff);
            ldsm4(al[t], aAdL[t] + aOff);
        }
        #pragma unroll
        for (int p = 0; p < 2; ++p) {
            ldsm4t(bh[p], bAdH[p] + bOff);
            ldsm4t(bl[p], bAdL[p] + bOff);
        }
        #pragma unroll
        for (int t = 0; t < 2; ++t) {
            #pragma unroll
            for (int nt = 0; nt < 4; ++nt) {
                const unsigned* Bh2 = &bh[nt >> 1][(nt & 1) * 2];
                const unsigned* Bl2 = &bl[nt >> 1][(nt & 1) * 2];
                mma_bf16(acc[t][nt], ah[t], Bh2);
                mma_bf16(acc[t][nt], ah[t], Bl2);
                mma_bf16(acc[t][nt], al[t], Bh2);
            }
        }
        if (it + 1 < niter) sstore((it + 1) & 1);
    }

    #pragma unroll
    for (int t = 0; t < 2; ++t) {
        int mB = wm * 32 + t * 16 + (lane >> 2);
        #pragma unroll
        for (int nt = 0; nt < 4; ++nt) {
            int nB = col0 + wn * 32 + nt * 8 + (lane & 3) * 2;
            float* c = acc[t][nt];
            #pragma unroll
            for (int e = 0; e < 4; ++e) {
                int gm = mB + (e >> 1) * 8;
                int gn = nB + (e & 1);
                if (gm < M && gn < N) {
                    size_t o = (size_t)gm * ldc + gn;
                    bf16 h, l; f2bf(c[e], h, l);
                    Ch[o] = h; Cl[o] = l;
                }
            }
        }
    }
}

__device__ __forceinline__ void bgemmB_bf(
    const bf16* __restrict__ Ah, const bf16* __restrict__ Al, int lda,
    const float* __restrict__ Bp, int ldb,
    float* __restrict__ Cp, int ldc,
    int M, int N, int K)
{
    __shared__ __align__(16) bf16 sAh[2][64][B_AP];
    __shared__ __align__(16) bf16 sAl[2][64][B_AP];
    __shared__ __align__(16) bf16 sBh[2][16][B_BP];
    __shared__ __align__(16) bf16 sBl[2][16][B_BP];

    const int tid  = threadIdx.x;
    const int lane = tid & 31;
    const int warp = tid >> 5;
    const int wm = warp & 1;
    const int wn = warp >> 1;
    const int col0 = blockIdx.x * 64;

    const int ar = tid >> 1;
    const int ac = (tid & 1) * 8;
    const int br = tid >> 3;
    const int bc = (tid & 7) * 8;

    float acc[2][4][4];
    #pragma unroll
    for (int t = 0; t < 2; ++t)
        #pragma unroll
        for (int n = 0; n < 4; ++n)
            #pragma unroll
            for (int e = 0; e < 4; ++e) acc[t][n][e] = 0.f;

    unsigned aAdH[2], aAdL[2], bAdH[2], bAdL[2];
    #pragma unroll
    for (int t = 0; t < 2; ++t) {
        int rr = wm * 32 + t * 16 + (lane & 15);
        int cc = (lane >> 4) * 8;
        aAdH[t] = (unsigned)__cvta_generic_to_shared(&sAh[0][rr][cc]);
        aAdL[t] = (unsigned)__cvta_generic_to_shared(&sAl[0][rr][cc]);
    }
    #pragma unroll
    for (int p = 0; p < 2; ++p) {
        int rr = (lane & 15);
        int cc = wn * 32 + p * 16 + (lane >> 4) * 8;
        bAdH[p] = (unsigned)__cvta_generic_to_shared(&sBh[0][rr][cc]);
        bAdL[p] = (unsigned)__cvta_generic_to_shared(&sBl[0][rr][cc]);
    }
    const unsigned aStg = 64u * B_AP * 2u;
    const unsigned bStg = 16u * B_BP * 2u;

    uint4 avh, avl;
    float4 bv[2];

    auto gload = [&](int kt) {
        int gr = min(ar, M - 1);
        size_t ao = (size_t)gr * lda + kt + ac;
        avh = *reinterpret_cast<const uint4*>(Ah + ao);
        avl = *reinterpret_cast<const uint4*>(Al + ao);
        #pragma unroll
        for (int p = 0; p < 2; ++p) {
            int gc = min(col0 + bc + p * 4, N - 4);
            bv[p] = *reinterpret_cast<const float4*>(&Bp[(size_t)(kt + br) * ldb + gc]);
        }
    };

    auto sstore = [&](int s) {
        *reinterpret_cast<uint4*>(&sAh[s][ar][ac]) = avh;
        *reinterpret_cast<uint4*>(&sAl[s][ar][ac]) = avl;
        #pragma unroll
        for (int p = 0; p < 2; ++p) {
            bf16 h0,l0,h1,l1,h2,l2,h3,l3;
            f2bf(bv[p].x, h0, l0); f2bf(bv[p].y, h1, l1);
            f2bf(bv[p].z, h2, l2); f2bf(bv[p].w, h3, l3);
            __nv_bfloat162 q;
            int c = bc + p * 4;
            q.x = h0; q.y = h1; *reinterpret_cast<__nv_bfloat162*>(&sBh[s][br][c])     = q;
            q.x = h2; q.y = h3; *reinterpret_cast<__nv_bfloat162*>(&sBh[s][br][c + 2]) = q;
            q.x = l0; q.y = l1; *reinterpret_cast<__nv_bfloat162*>(&sBl[s][br][c])     = q;
            q.x = l2; q.y = l3; *reinterpret_cast<__nv_bfloat162*>(&sBl[s][br][c + 2]) = q;
        }
    };

    const int niter = K / 16;
    gload(0);
    sstore(0);

    for (int it = 0; it < niter; ++it) {
        __syncthreads();
        if (it + 1 < niter) gload((it + 1) * 16);

        const int s = it & 1;
        const unsigned aOff = s * aStg, bOff = s * bStg;
        unsigned ah[2][4], al[2][4], bh[2][4], bl[2][4];
        #pragma unroll
        for (int t = 0; t < 2; ++t) {
            ldsm4(ah[t], aAdH[t] + aOff);
            ldsm4(al[t], aAdL[t] + aOff);
        }
        #pragma unroll
        for (int p = 0; p < 2; ++p) {
            ldsm4t(bh[p], bAdH[p] + bOff);
            ldsm4t(bl[p], bAdL[p] + bOff);
        }
        #pragma unroll
        for (int t = 0; t < 2; ++t) {
            #pragma unroll
            for (int nt = 0; nt < 4; ++nt) {
                const unsigned* Bh2 = &bh[nt >> 1][(nt & 1) * 2];
                const unsigned* Bl2 = &bl[nt >> 1][(nt & 1) * 2];
                mma_bf16(acc[t][nt], ah[t], Bh2);
                mma_bf16(acc[t][nt], ah[t], Bl2);
                mma_bf16(acc[t][nt], al[t], Bh2);
            }
        }
        if (it + 1 < niter) sstore((it + 1) & 1);
    }

    #pragma unroll
    for (int t = 0; t < 2; ++t) {
        int mB = wm * 32 + t * 16 + (lane >> 2);
        #pragma unroll
        for (int nt = 0; nt < 4; ++nt) {
            int nB = col0 + wn * 32 + nt * 8 + (lane & 3) * 2;
            float* c = acc[t][nt];
            #pragma unroll
            for (int e = 0; e < 4; ++e) {
                int gm = mB + (e >> 1) * 8;
                int gn = nB + (e & 1);
                if (gm < M && gn < N)
                    Cp[(size_t)gm * ldc + gn] = c[e];
            }
        }
    }
}

// ---------------------------------------------------------------------------
// Stage kernels
// ---------------------------------------------------------------------------
__global__ void __launch_bounds__(256, 2) k_gemm_A1(const float* __restrict__ R,
                                                    const float* __restrict__ x) {
    const int z = blockIdx.z;
    const int j = z % Cn;
    const int i = (z / Cn) % Cn;
    const int b = z / (Cn * Cn);
    const float* A  = R + (size_t)(i * Cn + j) * Dn * Dn;
    const float* Bp = x + (size_t)(b * Cn + j) * Dn * Dn;
    size_t to = (size_t)(b * Cn + i) * Dn * Kbig + (size_t)j * Dn;
    bgemmA_f32(A, Dn, Bp, Dn, g_th + to, g_tl + to, Kbig, Dn, Dn, Dn);
}

__global__ void __launch_bounds__(256, 2) k_gemm_A2() {
    const int z = blockIdx.z;                 // b*Cn + i
    const int i = z % Cn;
    size_t ao = (size_t)z * Dn * Kbig;
    size_t bo = (size_t)i * Cn * Dn * Dn;
    size_t co = (size_t)z * Dn * Dn;
    bgemmA_pre(g_th + ao, g_tl + ao, Kbig, g_Rth + bo, g_Rtl + bo, Dn,
               g_yh + co, g_yl + co, Dn, Dn, Dn, Kbig);
}

__global__ void __launch_bounds__(128) k_gemm_B1(const float* __restrict__ P) {
    const int z = blockIdx.z;                 // (b*OCn + i)*Cn + j
    const int j = z % Cn;
    const int i = (z / Cn) % OCn;
    const int b = z / (Cn * OCn);
    const float* A = P + (size_t)(i * Cn + j) * OHn * Dn;
    size_t bo = (size_t)(b * Cn + j) * Dn * Dn;
    size_t co = (size_t)(b * OCn + i) * OHn * Kbig + (size_t)j * Dn;
    bgemmB_fb(A, Dn, g_yh + bo, g_yl + bo, Dn,
              g_uh + co, g_ul + co, Kbig, OHn, Dn, Dn);
}

// B2 split-K: blockIdx.y = k-chunk (4 chunks of 768); writes fp32 partials.
__global__ void __launch_bounds__(128) k_gemm_B2(const float* __restrict__ PT) {
    const int z  = blockIdx.z;                // b*OCn + i
    const int ky = blockIdx.y;                // 0..3
    const int i  = z % OCn;
    const int kt0 = ky * (Kbig / 4);          // 768
    size_t ao = (size_t)z * OHn * Kbig + kt0;
    const float* Bp = PT + (size_t)i * (size_t)Kbig * OWn + (size_t)kt0 * OWn;
    float* Cp = g_p + ((size_t)ky * (Bn * OCn) + z) * OHn * OWn;
    bgemmB_bf(g_uh + ao, g_ul + ao, Kbig, Bp, OWn, Cp, OWn, OHn, OWn, Kbig / 4);
}

// Sum the 4 partials (fixed order -> deterministic)
__global__ void k_reduce(float* __restrict__ out) {
    const size_t n = (size_t)Bn * OCn * OHn * OWn;     // 320000
    size_t idx = (size_t)blockIdx.x * blockDim.x + threadIdx.x;
    if (idx >= n) return;
    float s = g_p[idx];
    s += g_p[n + idx];
    s += g_p[2 * n + idx];
    s += g_p[3 * n + idx];
    out[idx] = s;
}

// ---------------------------------------------------------------------------
extern "C" void kernel_launch(void* const* d_in, const int* in_sizes, int n_in,
                              void* d_out, int out_size) {
    const float* x  = (const float*)d_in[0];
    const float* R  = (const float*)d_in[1];
    const float* P  = (const float*)d_in[2];
    const float* PT = (const float*)d_in[3];
    float* out = (float*)d_out;

    k_cvtT<<<dim3(6, 6, 256), dim3(32, 8)>>>(R);
    k_gemm_A1<<<dim3(2, 1, Bn * Cn * Cn), 256>>>(R, x);
    k_gemm_A2<<<dim3(2, 1, Bn * Cn), 256>>>();
    k_gemm_B1<<<dim3(3, 1, Bn * OCn * Cn), 128>>>(P);
    k_gemm_B2<<<dim3(4, 4, Bn * OCn), 128>>>(PT);
    k_reduce<<<(Bn * OCn * OHn * OWn + 255) / 256, 256>>>(out);
}

// round 15
// speedup vs baseline: 1.4233x; 1.4233x over previous
#include <cuda_runtime.h>
#include <cuda_bf16.h>
#include <cstdint>

// Problem dims
#define Bn 8
#define Cn 16
#define Dn 192
#define OCn 4
#define OHn 50
#define OWn 200
#define Kbig (Cn*Dn)   // 3072

typedef __nv_bfloat16 bf16;

#define R_ELEMS ((size_t)Cn*Cn*Dn*Dn)
#define T_ELEMS ((size_t)Bn*Cn*Dn*Kbig)
#define Y_ELEMS ((size_t)Bn*Cn*Dn*Dn)
#define U_ELEMS ((size_t)Bn*OCn*OHn*Kbig)

// Scratch — packed hi|lo bf16 in ONE uint per element (4 B/elem, same bytes
// and same load geometry as the verified fp32 scratch; statics = 383 MB).
__device__ __align__(256) unsigned g_Rt[R_ELEMS];   // Rt packed
__device__ __align__(256) unsigned g_t [T_ELEMS];   // t  packed
__device__ __align__(256) unsigned g_y [Y_ELEMS];   // y  packed
__device__ __align__(256) unsigned g_u [U_ELEMS];   // u  packed
__device__ float g_p[(size_t)4*Bn*OCn*OHn*OWn];     // B2 split-K partials (fp32)

// ---------------------------------------------------------------------------
__device__ __forceinline__ void f2bf(float v, bf16& h, bf16& l) {
    h = __float2bfloat16_rn(v);
    l = __float2bfloat16_rn(v - __bfloat162float(h));
}
__device__ __forceinline__ unsigned pack2(float v) {
    bf16 h, l; f2bf(v, h, l);
    return (unsigned)__bfloat16_as_ushort(h) | ((unsigned)__bfloat16_as_ushort(l) << 16);
}
__device__ __forceinline__ void mma_bf16(float* c, const unsigned* a, const unsigned* b) {
    asm volatile(
        "mma.sync.aligned.m16n8k16.row.col.f32.bf16.bf16.f32 "
        "{%0,%1,%2,%3}, {%4,%5,%6,%7}, {%8,%9}, {%0,%1,%2,%3};\n"
        : "+f"(c[0]), "+f"(c[1]), "+f"(c[2]), "+f"(c[3])
        : "r"(a[0]), "r"(a[1]), "r"(a[2]), "r"(a[3]), "r"(b[0]), "r"(b[1]));
}
__device__ __forceinline__ void ldsm4(unsigned* r, unsigned addr) {
    asm volatile("ldmatrix.sync.aligned.m8n8.x4.shared.b16 {%0,%1,%2,%3}, [%4];\n"
                 : "=r"(r[0]), "=r"(r[1]), "=r"(r[2]), "=r"(r[3]) : "r"(addr));
}
__device__ __forceinline__ void ldsm4t(unsigned* r, unsigned addr) {
    asm volatile("ldmatrix.sync.aligned.m8n8.x4.trans.shared.b16 {%0,%1,%2,%3}, [%4];\n"
                 : "=r"(r[0]), "=r"(r[1]), "=r"(r[2]), "=r"(r[3]) : "r"(addr));
}

// ---------------------------------------------------------------------------
// Transpose-convert: Rt[i][j][q][n] = R[i][j][n][q], fp32 -> packed hi|lo
// ---------------------------------------------------------------------------
__global__ void k_cvtT(const float* __restrict__ R) {
    __shared__ float tile[32][33];
    const int mat = blockIdx.z;
    const float* __restrict__ src = R + (size_t)mat * Dn * Dn;
    unsigned* __restrict__ dst = g_Rt + (size_t)mat * Dn * Dn;
    const int x0 = blockIdx.x * 32, y0 = blockIdx.y * 32;
    const int tx = threadIdx.x, ty = threadIdx.y;     // 32 x 8
    #pragma unroll
    for (int r = 0; r < 32; r += 8)
        tile[ty + r][tx] = src[(size_t)(y0 + ty + r) * Dn + x0 + tx];
    __syncthreads();
    #pragma unroll
    for (int r = 0; r < 32; r += 8)
        dst[(size_t)(x0 + ty + r) * Dn + y0 + tx] = pack2(tile[tx][ty + r]);
}

// ===========================================================================
// A-stage shape (VERIFIED R13): 192x96 CTA, 256 thr, 8 warps 4m x 2n (48x48),
// BK=16, double buffer, one sync/iter.
//   bgemmA_f32: fp32 operands, in-loop f2bf (A1) -> packed out
//   bgemmA_pk : packed operands, PRMT deinterleave (A2) -> packed out
// ===========================================================================
#define A_AP 40
#define A_BP 104

__device__ __forceinline__ void bgemmA_f32(
    const float* __restrict__ A, int lda,
    const float* __restrict__ Bp, int ldb,
    unsigned* __restrict__ Cp, int ldc,
    int M, int N, int K)
{
    __shared__ __align__(16) bf16 sA [2][192][A_AP];
    __shared__ __align__(16) bf16 sBh[2][16][A_BP];
    __shared__ __align__(16) bf16 sBl[2][16][A_BP];

    const int tid  = threadIdx.x;
    const int lane = tid & 31;
    const int warp = tid >> 5;
    const int wm = warp & 3;
    const int wn = warp >> 2;
    const int col0 = blockIdx.x * 96;

    const int ar = tid >> 2;
    const int ac = (tid & 3) * 4;
    const int bact = tid < 192;
    const int br = tid / 12;
    const int bc = (tid % 12) * 8;

    float acc[3][6][4];
    #pragma unroll
    for (int t = 0; t < 3; ++t)
        #pragma unroll
        for (int n = 0; n < 6; ++n)
            #pragma unroll
            for (int e = 0; e < 4; ++e) acc[t][n][e] = 0.f;

    unsigned aAd[3], bAdH[3], bAdL[3];
    #pragma unroll
    for (int t = 0; t < 3; ++t) {
        int rr = wm * 48 + t * 16 + (lane & 15);
        int cc = (lane >> 4) * 8;
        aAd[t] = (unsigned)__cvta_generic_to_shared(&sA[0][rr][cc]);
    }
    #pragma unroll
    for (int f = 0; f < 3; ++f) {
        int rr = lane & 15;
        int cc = wn * 48 + f * 16 + (lane >> 4) * 8;
        bAdH[f] = (unsigned)__cvta_generic_to_shared(&sBh[0][rr][cc]);
        bAdL[f] = (unsigned)__cvta_generic_to_shared(&sBl[0][rr][cc]);
    }
    const unsigned aStg = 192u * A_AP * 2u;
    const unsigned bStg = 16u * A_BP * 2u;

    float4 av[3], bv[2];

    auto gload = [&](int kt) {
        #pragma unroll
        for (int p = 0; p < 3; ++p) {
            int gr = min(ar + p * 64, M - 1);
            av[p] = *reinterpret_cast<const float4*>(&A[(size_t)gr * lda + kt + ac]);
        }
        if (bact) {
            int gc = min(col0 + bc, N - 8);
            size_t bo = (size_t)(kt + br) * ldb + gc;
            bv[0] = *reinterpret_cast<const float4*>(&Bp[bo]);
            bv[1] = *reinterpret_cast<const float4*>(&Bp[bo + 4]);
        }
    };

    auto sstore = [&](int s) {
        #pragma unroll
        for (int p = 0; p < 3; ++p) {
            int r = ar + p * 64;
            bf16 h0,l0,h1,l1,h2,l2,h3,l3;
            f2bf(av[p].x, h0, l0); f2bf(av[p].y, h1, l1);
            f2bf(av[p].z, h2, l2); f2bf(av[p].w, h3, l3);
            __nv_bfloat162 q;
            q.x = h0; q.y = h1; *reinterpret_cast<__nv_bfloat162*>(&sA[s][r][ac])          = q;
            q.x = h2; q.y = h3; *reinterpret_cast<__nv_bfloat162*>(&sA[s][r][ac + 2])      = q;
            q.x = l0; q.y = l1; *reinterpret_cast<__nv_bfloat162*>(&sA[s][r][16 + ac])     = q;
            q.x = l2; q.y = l3; *reinterpret_cast<__nv_bfloat162*>(&sA[s][r][16 + ac + 2]) = q;
        }
        if (bact) {
            #pragma unroll
            for (int p = 0; p < 2; ++p) {
                bf16 h0,l0,h1,l1,h2,l2,h3,l3;
                f2bf(bv[p].x, h0, l0); f2bf(bv[p].y, h1, l1);
                f2bf(bv[p].z, h2, l2); f2bf(bv[p].w, h3, l3);
                __nv_bfloat162 q;
                int c = bc + p * 4;
                q.x = h0; q.y = h1; *reinterpret_cast<__nv_bfloat162*>(&sBh[s][br][c])     = q;
                q.x = h2; q.y = h3; *reinterpret_cast<__nv_bfloat162*>(&sBh[s][br][c + 2]) = q;
                q.x = l0; q.y = l1; *reinterpret_cast<__nv_bfloat162*>(&sBl[s][br][c])     = q;
                q.x = l2; q.y = l3; *reinterpret_cast<__nv_bfloat162*>(&sBl[s][br][c + 2]) = q;
            }
        }
    };

    const int niter = K / 16;
    gload(0);
    sstore(0);

    for (int it = 0; it < niter; ++it) {
        __syncthreads();
        if (it + 1 < niter) gload((it + 1) * 16);

        const int s = it & 1;
        const unsigned aOff = s * aStg, bOff = s * bStg;
        unsigned ah[3][4], al[3][4], bh[3][4], bl[3][4];
        #pragma unroll
        for (int t = 0; t < 3; ++t) {
            ldsm4(ah[t], aAd[t] + aOff);
            ldsm4(al[t], aAd[t] + aOff + 32);
        }
        #pragma unroll
        for (int f = 0; f < 3; ++f) {
            ldsm4t(bh[f], bAdH[f] + bOff);
            ldsm4t(bl[f], bAdL[f] + bOff);
        }
        #pragma unroll
        for (int t = 0; t < 3; ++t) {
            #pragma unroll
            for (int nt = 0; nt < 6; ++nt) {
                const unsigned* Bh = &bh[nt >> 1][(nt & 1) * 2];
                const unsigned* Bl = &bl[nt >> 1][(nt & 1) * 2];
                mma_bf16(acc[t][nt], ah[t], Bh);
                mma_bf16(acc[t][nt], ah[t], Bl);
                mma_bf16(acc[t][nt], al[t], Bh);
            }
        }
        if (it + 1 < niter) sstore((it + 1) & 1);
    }

    #pragma unroll
    for (int t = 0; t < 3; ++t) {
        int mB = wm * 48 + t * 16 + (lane >> 2);
        #pragma unroll
        for (int nt = 0; nt < 6; ++nt) {
            int nB = col0 + wn * 48 + nt * 8 + (lane & 3) * 2;
            float* c = acc[t][nt];
            #pragma unroll
            for (int e = 0; e < 4; ++e) {
                int gm = mB + (e >> 1) * 8;
                int gn = nB + (e & 1);
                if (gm < M && gn < N)
                    Cp[(size_t)gm * ldc + gn] = pack2(c[e]);
            }
        }
    }
}

__device__ __forceinline__ void bgemmA_pk(
    const unsigned* __restrict__ A, int lda,
    const unsigned* __restrict__ Bp, int ldb,
    unsigned* __restrict__ Cp, int ldc,
    int M, int N, int K)
{
    __shared__ __align__(16) bf16 sA [2][192][A_AP];
    __shared__ __align__(16) bf16 sBh[2][16][A_BP];
    __shared__ __align__(16) bf16 sBl[2][16][A_BP];

    const int tid  = threadIdx.x;
    const int lane = tid & 31;
    const int warp = tid >> 5;
    const int wm = warp & 3;
    const int wn = warp >> 2;
    const int col0 = blockIdx.x * 96;

    const int ar = tid >> 2;
    const int ac = (tid & 3) * 4;
    const int bact = tid < 192;
    const int br = tid / 12;
    const int bc = (tid % 12) * 8;

    float acc[3][6][4];
    #pragma unroll
    for (int t = 0; t < 3; ++t)
        #pragma unroll
        for (int n = 0; n < 6; ++n)
            #pragma unroll
            for (int e = 0; e < 4; ++e) acc[t][n][e] = 0.f;

    unsigned aAd[3], bAdH[3], bAdL[3];
    #pragma unroll
    for (int t = 0; t < 3; ++t) {
        int rr = wm * 48 + t * 16 + (lane & 15);
        int cc = (lane >> 4) * 8;
        aAd[t] = (unsigned)__cvta_generic_to_shared(&sA[0][rr][cc]);
    }
    #pragma unroll
    for (int f = 0; f < 3; ++f) {
        int rr = lane & 15;
        int cc = wn * 48 + f * 16 + (lane >> 4) * 8;
        bAdH[f] = (unsigned)__cvta_generic_to_shared(&sBh[0][rr][cc]);
        bAdL[f] = (unsigned)__cvta_generic_to_shared(&sBl[0][rr][cc]);
    }
    const unsigned aStg = 192u * A_AP * 2u;
    const unsigned bStg = 16u * A_BP * 2u;

    uint4 avp[3], bvp[2];

    auto gload = [&](int kt) {
        #pragma unroll
        for (int p = 0; p < 3; ++p) {
            int gr = min(ar + p * 64, M - 1);
            avp[p] = *reinterpret_cast<const uint4*>(&A[(size_t)gr * lda + kt + ac]);
        }
        if (bact) {
            int gc = min(col0 + bc, N - 8);
            size_t bo = (size_t)(kt + br) * ldb + gc;
            bvp[0] = *reinterpret_cast<const uint4*>(&Bp[bo]);
            bvp[1] = *reinterpret_cast<const uint4*>(&Bp[bo + 4]);
        }
    };

    auto sstore = [&](int s) {
        #pragma unroll
        for (int p = 0; p < 3; ++p) {
            int r = ar + p * 64;
            unsigned hi01 = __byte_perm(avp[p].x, avp[p].y, 0x5410);
            unsigned hi23 = __byte_perm(avp[p].z, avp[p].w, 0x5410);
            unsigned lo01 = __byte_perm(avp[p].x, avp[p].y, 0x7632);
            unsigned lo23 = __byte_perm(avp[p].z, avp[p].w, 0x7632);
            *reinterpret_cast<uint2*>(&sA[s][r][ac])      = make_uint2(hi01, hi23);
            *reinterpret_cast<uint2*>(&sA[s][r][16 + ac]) = make_uint2(lo01, lo23);
        }
        if (bact) {
            #pragma unroll
            for (int q = 0; q < 2; ++q) {
                int c = bc + q * 4;
                unsigned hiA = __byte_perm(bvp[q].x, bvp[q].y, 0x5410);
                unsigned hiB = __byte_perm(bvp[q].z, bvp[q].w, 0x5410);
                unsigned loA = __byte_perm(bvp[q].x, bvp[q].y, 0x7632);
                unsigned loB = __byte_perm(bvp[q].z, bvp[q].w, 0x7632);
                *reinterpret_cast<uint2*>(&sBh[s][br][c]) = make_uint2(hiA, hiB);
                *reinterpret_cast<uint2*>(&sBl[s][br][c]) = make_uint2(loA, loB);
            }
        }
    };

    const int niter = K / 16;
    gload(0);
    sstore(0);

    for (int it = 0; it < niter; ++it) {
        __syncthreads();
        if (it + 1 < niter) gload((it + 1) * 16);

        const int s = it & 1;
        const unsigned aOff = s * aStg, bOff = s * bStg;
        unsigned ah[3][4], al[3][4], bh[3][4], bl[3][4];
        #pragma unroll
        for (int t = 0; t < 3; ++t) {
            ldsm4(ah[t], aAd[t] + aOff);
            ldsm4(al[t], aAd[t] + aOff + 32);
        }
        #pragma unroll
        for (int f = 0; f < 3; ++f) {
            ldsm4t(bh[f], bAdH[f] + bOff);
            ldsm4t(bl[f], bAdL[f] + bOff);
        }
        #pragma unroll
        for (int t = 0; t < 3; ++t) {
            #pragma unroll
            for (int nt = 0; nt < 6; ++nt) {
                const unsigned* Bh = &bh[nt >> 1][(nt & 1) * 2];
                const unsigned* Bl = &bl[nt >> 1][(nt & 1) * 2];
                mma_bf16(acc[t][nt], ah[t], Bh);
                mma_bf16(acc[t][nt], ah[t], Bl);
                mma_bf16(acc[t][nt], al[t], Bh);
            }
        }
        if (it + 1 < niter) sstore((it + 1) & 1);
    }

    #pragma unroll
    for (int t = 0; t < 3; ++t) {
        int mB = wm * 48 + t * 16 + (lane >> 2);
        #pragma unroll
        for (int nt = 0; nt < 6; ++nt) {
            int nB = col0 + wn * 48 + nt * 8 + (lane & 3) * 2;
            float* c = acc[t][nt];
            #pragma unroll
            for (int e = 0; e < 4; ++e) {
                int gm = mB + (e >> 1) * 8;
                int gn = nB + (e & 1);
                if (gm < M && gn < N)
                    Cp[(size_t)gm * ldc + gn] = pack2(c[e]);
            }
        }
    }
}

// ===========================================================================
// B-stage shape (VERIFIED R11/R13): 64x64 CTA, 128 threads, BK=16, dbl buf.
//   bgemmB_fp: A fp32 in-loop f2bf, B packed (PRMT)  -> packed out   (B1)
//   bgemmB_pf: A packed (PRMT), B fp32 in-loop f2bf  -> fp32 out     (B2)
// ===========================================================================
#define B_AP 24
#define B_BP 72

__device__ __forceinline__ void bgemmB_fp(
    const float* __restrict__ A, int lda,
    const unsigned* __restrict__ Bp, int ldb,
    unsigned* __restrict__ Cp, int ldc,
    int M, int N, int K)
{
    __shared__ __align__(16) bf16 sAh[2][64][B_AP];
    __shared__ __align__(16) bf16 sAl[2][64][B_AP];
    __shared__ __align__(16) bf16 sBh[2][16][B_BP];
    __shared__ __align__(16) bf16 sBl[2][16][B_BP];

    const int tid  = threadIdx.x;
    const int lane = tid & 31;
    const int warp = tid >> 5;
    const int wm = warp & 1;
    const int wn = warp >> 1;
    const int col0 = blockIdx.x * 64;

    const int ar = tid >> 1;
    const int ac = (tid & 1) * 8;
    const int br = tid >> 3;
    const int bc = (tid & 7) * 8;

    float acc[2][4][4];
    #pragma unroll
    for (int t = 0; t < 2; ++t)
        #pragma unroll
        for (int n = 0; n < 4; ++n)
            #pragma unroll
            for (int e = 0; e < 4; ++e) acc[t][n][e] = 0.f;

    unsigned aAdH[2], aAdL[2], bAdH[2], bAdL[2];
    #pragma unroll
    for (int t = 0; t < 2; ++t) {
        int rr = wm * 32 + t * 16 + (lane & 15);
        int cc = (lane >> 4) * 8;
        aAdH[t] = (unsigned)__cvta_generic_to_shared(&sAh[0][rr][cc]);
        aAdL[t] = (unsigned)__cvta_generic_to_shared(&sAl[0][rr][cc]);
    }
    #pragma unroll
    for (int p = 0; p < 2; ++p) {
        int rr = (lane & 15);
        int cc = wn * 32 + p * 16 + (lane >> 4) * 8;
        bAdH[p] = (unsigned)__cvta_generic_to_shared(&sBh[0][rr][cc]);
        bAdL[p] = (unsigned)__cvta_generic_to_shared(&sBl[0][rr][cc]);
    }
    const unsigned aStg = 64u * B_AP * 2u;
    const unsigned bStg = 16u * B_BP * 2u;

    float4 av[2];
    uint4 bvp[2];

    auto gload = [&](int kt) {
        int gr = min(ar, M - 1);
        #pragma unroll
        for (int p = 0; p < 2; ++p)
            av[p] = *reinterpret_cast<const float4*>(&A[(size_t)gr * lda + kt + ac + p * 4]);
        int gc = min(col0 + bc, N - 8);
        size_t bo = (size_t)(kt + br) * ldb + gc;
        bvp[0] = *reinterpret_cast<const uint4*>(&Bp[bo]);
        bvp[1] = *reinterpret_cast<const uint4*>(&Bp[bo + 4]);
    };

    auto sstore = [&](int s) {
        #pragma unroll
        for (int p = 0; p < 2; ++p) {
            bf16 h0,l0,h1,l1,h2,l2,h3,l3;
            f2bf(av[p].x, h0, l0); f2bf(av[p].y, h1, l1);
            f2bf(av[p].z, h2, l2); f2bf(av[p].w, h3, l3);
            __nv_bfloat162 q;
            int c = ac + p * 4;
            q.x = h0; q.y = h1; *reinterpret_cast<__nv_bfloat162*>(&sAh[s][ar][c])     = q;
            q.x = h2; q.y = h3; *reinterpret_cast<__nv_bfloat162*>(&sAh[s][ar][c + 2]) = q;
            q.x = l0; q.y = l1; *reinterpret_cast<__nv_bfloat162*>(&sAl[s][ar][c])     = q;
            q.x = l2; q.y = l3; *reinterpret_cast<__nv_bfloat162*>(&sAl[s][ar][c + 2]) = q;
        }
        #pragma unroll
        for (int q = 0; q < 2; ++q) {
            int c = bc + q * 4;
            unsigned hiA = __byte_perm(bvp[q].x, bvp[q].y, 0x5410);
            unsigned hiB = __byte_perm(bvp[q].z, bvp[q].w, 0x5410);
            unsigned loA = __byte_perm(bvp[q].x, bvp[q].y, 0x7632);
            unsigned loB = __byte_perm(bvp[q].z, bvp[q].w, 0x7632);
            *reinterpret_cast<uint2*>(&sBh[s][br][c]) = make_uint2(hiA, hiB);
            *reinterpret_cast<uint2*>(&sBl[s][br][c]) = make_uint2(loA, loB);
        }
    };

    const int niter = K / 16;
    gload(0);
    sstore(0);

    for (int it = 0; it < niter; ++it) {
        __syncthreads();
        if (it + 1 < niter) gload((it + 1) * 16);

        const int s = it & 1;
        const unsigned aOff = s * aStg, bOff = s * bStg;
        unsigned ah[2][4], al[2][4], bh[2][4], bl[2][4];
        #pragma unroll
        for (int t = 0; t < 2; ++t) {
            ldsm4(ah[t], aAdH[t] + aOff);
            ldsm4(al[t], aAdL[t] + aOff);
        }
        #pragma unroll
        for (int p = 0; p < 2; ++p) {
            ldsm4t(bh[p], bAdH[p] + bOff);
            ldsm4t(bl[p], bAdL[p] + bOff);
        }
        #pragma unroll
        for (int t = 0; t < 2; ++t) {
            #pragma unroll
            for (int nt = 0; nt < 4; ++nt) {
                const unsigned* Bh2 = &bh[nt >> 1][(nt & 1) * 2];
                const unsigned* Bl2 = &bl[nt >> 1][(nt & 1) * 2];
                mma_bf16(acc[t][nt], ah[t], Bh2);
                mma_bf16(acc[t][nt], ah[t], Bl2);
                mma_bf16(acc[t][nt], al[t], Bh2);
            }
        }
        if (it + 1 < niter) sstore((it + 1) & 1);
    }

    #pragma unroll
    for (int t = 0; t < 2; ++t) {
        int mB = wm * 32 + t * 16 + (lane >> 2);
        #pragma unroll
        for (int nt = 0; nt < 4; ++nt) {
            int nB = col0 + wn * 32 + nt * 8 + (lane & 3) * 2;
            float* c = acc[t][nt];
            #pragma unroll
            for (int e = 0; e < 4; ++e) {
                int gm = mB + (e >> 1) * 8;
                int gn = nB + (e & 1);
                if (gm < M && gn < N)
                    Cp[(size_t)gm * ldc + gn] = pack2(c[e]);
            }
        }
    }
}

__device__ __forceinline__ void bgemmB_pf(
    const unsigned* __restrict__ A, int lda,
    const float* __restrict__ Bp, int ldb,
    float* __restrict__ Cp, int ldc,
    int M, int N, int K)
{
    __shared__ __align__(16) bf16 sAh[2][64][B_AP];
    __shared__ __align__(16) bf16 sAl[2][64][B_AP];
    __shared__ __align__(16) bf16 sBh[2][16][B_BP];
    __shared__ __align__(16) bf16 sBl[2][16][B_BP];

    const int tid  = threadIdx.x;
    const int lane = tid & 31;
    const int warp = tid >> 5;
    const int wm = warp & 1;
    const int wn = warp >> 1;
    const int col0 = blockIdx.x * 64;

    const int ar = tid >> 1;
    const int ac = (tid & 1) * 8;
    const int br = tid >> 3;
    const int bc = (tid & 7) * 8;

    float acc[2][4][4];
    #pragma unroll
    for (int t = 0; t < 2; ++t)
        #pragma unroll
        for (int n = 0; n < 4; ++n)
            #pragma unroll
            for (int e = 0; e < 4; ++e) acc[t][n][e] = 0.f;

    unsigned aAdH[2], aAdL[2], bAdH[2], bAdL[2];
    #pragma unroll
    for (int t = 0; t < 2; ++t) {
        int rr = wm * 32 + t * 16 + (lane & 15);
        int cc = (lane >> 4) * 8;
        aAdH[t] = (unsigned)__cvta_generic_to_shared(&sAh[0][rr][cc]);
        aAdL[t] = (unsigned)__cvta_generic_to_shared(&sAl[0][rr][cc]);
    }
    #pragma unroll
    for (int p = 0; p < 2; ++p) {
        int rr = (lane & 15);
        int cc = wn * 32 + p * 16 + (lane >> 4) * 8;
        bAdH[p] = (unsigned)__cvta_generic_to_shared(&sBh[0][rr][cc]);
        bAdL[p] = (unsigned)__cvta_generic_to_shared(&sBl[0][rr][cc]);
    }
    const unsigned aStg = 64u * B_AP * 2u;
    const unsigned bStg = 16u * B_BP * 2u;

    uint4 avp[2];
    float4 bv[2];

    auto gload = [&](int kt) {
        int gr = min(ar, M - 1);
        size_t ao = (size_t)gr * lda + kt + ac;
        avp[0] = *reinterpret_cast<const uint4*>(&A[ao]);
        avp[1] = *reinterpret_cast<const uint4*>(&A[ao + 4]);
        #pragma unroll
        for (int p = 0; p < 2; ++p) {
            int gc = col0 + bc + p * 4;
            bv[p] = (gc < N) ? *reinterpret_cast<const float4*>(&Bp[(size_t)(kt + br) * ldb + gc])
                             : make_float4(0.f, 0.f, 0.f, 0.f);
        }
    };

    auto sstore = [&](int s) {
        #pragma unroll
        for (int q = 0; q < 2; ++q) {
            int c = ac + q * 4;
            unsigned hiA = __byte_perm(avp[q].x, avp[q].y, 0x5410);
            unsigned hiB = __byte_perm(avp[q].z, avp[q].w, 0x5410);
            unsigned loA = __byte_perm(avp[q].x, avp[q].y, 0x7632);
            unsigned loB = __byte_perm(avp[q].z, avp[q].w, 0x7632);
            *reinterpret_cast<uint2*>(&sAh[s][ar][c]) = make_uint2(hiA, hiB);
            *reinterpret_cast<uint2*>(&sAl[s][ar][c]) = make_uint2(loA, loB);
        }
        #pragma unroll
        for (int p = 0; p < 2; ++p) {
            bf16 h0,l0,h1,l1,h2,l2,h3,l3;
            f2bf(bv[p].x, h0, l0); f2bf(bv[p].y, h1, l1);
            f2bf(bv[p].z, h2, l2); f2bf(bv[p].w, h3, l3);
            __nv_bfloat162 q;
            int c = bc + p * 4;
            q.x = h0; q.y = h1; *reinterpret_cast<__nv_bfloat162*>(&sBh[s][br][c])     = q;
            q.x = h2; q.y = h3; *reinterpret_cast<__nv_bfloat162*>(&sBh[s][br][c + 2]) = q;
            q.x = l0; q.y = l1; *reinterpret_cast<__nv_bfloat162*>(&sBl[s][br][c])     = q;
            q.x = l2; q.y = l3; *reinterpret_cast<__nv_bfloat162*>(&sBl[s][br][c + 2]) = q;
        }
    };

    const int niter = K / 16;
    gload(0);
    sstore(0);

    for (int it = 0; it < niter; ++it) {
        __syncthreads();
        if (it + 1 < niter) gload((it + 1) * 16);

        const int s = it & 1;
        const unsigned aOff = s * aStg, bOff = s * bStg;
        unsigned ah[2][4], al[2][4], bh[2][4], bl[2][4];
        #pragma unroll
        for (int t = 0; t < 2; ++t) {
            ldsm4(ah[t], aAdH[t] + aOff);
            ldsm4(al[t], aAdL[t] + aOff);
        }
        #pragma unroll
        for (int p = 0; p < 2; ++p) {
            ldsm4t(bh[p], bAdH[p] + bOff);
            ldsm4t(bl[p], bAdL[p] + bOff);
        }
        #pragma unroll
        for (int t = 0; t < 2; ++t) {
            #pragma unroll
            for (int nt = 0; nt < 4; ++nt) {
                const unsigned* Bh2 = &bh[nt >> 1][(nt & 1) * 2];
                const unsigned* Bl2 = &bl[nt >> 1][(nt & 1) * 2];
                mma_bf16(acc[t][nt], ah[t], Bh2);
                mma_bf16(acc[t][nt], ah[t], Bl2);
                mma_bf16(acc[t][nt], al[t], Bh2);
            }
        }
        if (it + 1 < niter) sstore((it + 1) & 1);
    }

    #pragma unroll
    for (int t = 0; t < 2; ++t) {
        int mB = wm * 32 + t * 16 + (lane >> 2);
        #pragma unroll
        for (int nt = 0; nt < 4; ++nt) {
            int nB = col0 + wn * 32 + nt * 8 + (lane & 3) * 2;
            float* c = acc[t][nt];
            #pragma unroll
            for (int e = 0; e < 4; ++e) {
                int gm = mB + (e >> 1) * 8;
                int gn = nB + (e & 1);
                if (gm < M && gn < N)
                    Cp[(size_t)gm * ldc + gn] = c[e];
            }
        }
    }
}

// ---------------------------------------------------------------------------
// Stage kernels
// ---------------------------------------------------------------------------
__global__ void __launch_bounds__(256, 2) k_gemm_A1(const float* __restrict__ R,
                                                    const float* __restrict__ x) {
    const int z = blockIdx.z;
    const int j = z % Cn;
    const int i = (z / Cn) % Cn;
    const int b = z / (Cn * Cn);
    const float* A  = R + (size_t)(i * Cn + j) * Dn * Dn;
    const float* Bp = x + (size_t)(b * Cn + j) * Dn * Dn;
    size_t to = (size_t)(b * Cn + i) * Dn * Kbig + (size_t)j * Dn;
    bgemmA_f32(A, Dn, Bp, Dn, g_t + to, Kbig, Dn, Dn, Dn);
}

__global__ void __launch_bounds__(256, 2) k_gemm_A2() {
    const int z = blockIdx.z;                 // b*Cn + i
    const int i = z % Cn;
    size_t ao = (size_t)z * Dn * Kbig;
    size_t bo = (size_t)i * Cn * Dn * Dn;
    size_t co = (size_t)z * Dn * Dn;
    bgemmA_pk(g_t + ao, Kbig, g_Rt + bo, Dn, g_y + co, Dn, Dn, Dn, Kbig);
}

__global__ void __launch_bounds__(128) k_gemm_B1(const float* __restrict__ P) {
    const int z = blockIdx.z;                 // (b*OCn + i)*Cn + j
    const int j = z % Cn;
    const int i = (z / Cn) % OCn;
    const int b = z / (Cn * OCn);
    const float* A = P + (size_t)(i * Cn + j) * OHn * Dn;
    size_t bo = (size_t)(b * Cn + j) * Dn * Dn;
    size_t co = (size_t)(b * OCn + i) * OHn * Kbig + (size_t)j * Dn;
    bgemmB_fp(A, Dn, g_y + bo, Dn, g_u + co, Kbig, OHn, Dn, Dn);
}

// B2 split-K: blockIdx.y = k-chunk (4 chunks of 768); writes fp32 partials.
__global__ void __launch_bounds__(128) k_gemm_B2(const float* __restrict__ PT) {
    const int z  = blockIdx.z;                // b*OCn + i
    const int ky = blockIdx.y;                // 0..3
    const int i  = z % OCn;
    const int kt0 = ky * (Kbig / 4);          // 768
    size_t ao = (size_t)z * OHn * Kbig + kt0;
    const float* Bp = PT + (size_t)i * (size_t)Kbig * OWn + (size_t)kt0 * OWn;
    float* Cp = g_p + ((size_t)ky * (Bn * OCn) + z) * OHn * OWn;
    bgemmB_pf(g_u + ao, Kbig, Bp, OWn, Cp, OWn, OHn, OWn, Kbig / 4);
}

// Sum the 4 partials (fixed order -> deterministic)
__global__ void k_reduce(float* __restrict__ out) {
    const size_t n = (size_t)Bn * OCn * OHn * OWn;     // 320000
    size_t idx = (size_t)blockIdx.x * blockDim.x + threadIdx.x;
    if (idx >= n) return;
    float s = g_p[idx];
    s += g_p[n + idx];
    s += g_p[2 * n + idx];
    s += g_p[3 * n + idx];
    out[idx] = s;
}

// ---------------------------------------------------------------------------
extern "C" void kernel_launch(void* const* d_in, const int* in_sizes, int n_in,
                              void* d_out, int out_size) {
    const float* x  = (const float*)d_in[0];
    const float* R  = (const float*)d_in[1];
    const float* P  = (const float*)d_in[2];
    const float* PT = (const float*)d_in[3];
    float* out = (float*)d_out;

    k_cvtT<<<dim3(6, 6, 256), dim3(32, 8)>>>(R);
    k_gemm_A1<<<dim3(2, 1, Bn * Cn * Cn), 256>>>(R, x);
    k_gemm_A2<<<dim3(2, 1, Bn * Cn), 256>>>();
    k_gemm_B1<<<dim3(3, 1, Bn * OCn * Cn), 128>>>(P);
    k_gemm_B2<<<dim3(4, 4, Bn * OCn), 128>>>(PT);
    k_reduce<<<(Bn * OCn * OHn * OWn + 255) / 256, 256>>>(out);
}